// round 14
// baseline (speedup 1.0000x reference)
#include <cuda_runtime.h>
#include <cuda_fp16.h>
#include <cstdint>

#define N_TOK 4096
#define NH 8
#define DH 16
#define DM 128
#define NSPLIT 4
// (1/sqrt(128)) * log2(e): softmax in exp2 domain
#define QSCL 0.12751743f

// fp16 scratch written by projection
__device__ __half g_qT[NH * N_TOK * DH];   // [head][tok][d]  (q, pre-scaled)
__device__ __half g_kT[NH * N_TOK * DH];   // [head][tok][d]
__device__ __half g_v [NH * DH * N_TOK];   // [head*16+d][tok]
// split-KV partials
__device__ float g_pnum[NSPLIT][NH][DH][N_TOK];   // 8 MB
__device__ float g_pden[NSPLIT][NH][N_TOK];       // 512 KB

// ---------------- helpers ----------------
__device__ __forceinline__ uint32_t cvt_h2(float hi, float lo) {
    uint32_t d;
    asm("cvt.rn.f16x2.f32 %0, %1, %2;" : "=r"(d) : "f"(hi), "f"(lo));
    return d;
}
__device__ __forceinline__ uint32_t ex2_h2(uint32_t a) {
    uint32_t d;
    asm("ex2.approx.f16x2 %0, %1;" : "=r"(d) : "r"(a));
    return d;
}
__device__ __forceinline__ void hmma(float& c0, float& c1, float& c2, float& c3,
                                     uint32_t a0, uint32_t a1, uint32_t a2, uint32_t a3,
                                     uint32_t b0, uint32_t b1) {
    asm volatile("mma.sync.aligned.m16n8k16.row.col.f32.f16.f16.f32 "
                 "{%0,%1,%2,%3}, {%4,%5,%6,%7}, {%8,%9}, {%0,%1,%2,%3};"
                 : "+f"(c0), "+f"(c1), "+f"(c2), "+f"(c3)
                 : "r"(a0), "r"(a1), "r"(a2), "r"(a3), "r"(b0), "r"(b1));
}
__device__ __forceinline__ void ldsm4(uint32_t& r0, uint32_t& r1,
                                      uint32_t& r2, uint32_t& r3, uint32_t addr) {
    asm volatile("ldmatrix.sync.aligned.m8n8.x4.shared.b16 {%0,%1,%2,%3}, [%4];"
                 : "=r"(r0), "=r"(r1), "=r"(r2), "=r"(r3) : "r"(addr));
}
__device__ __forceinline__ void ldsm4t(uint32_t& r0, uint32_t& r1,
                                       uint32_t& r2, uint32_t& r3, uint32_t addr) {
    asm volatile("ldmatrix.sync.aligned.m8n8.x4.trans.shared.b16 {%0,%1,%2,%3}, [%4];"
                 : "=r"(r0), "=r"(r1), "=r"(r2), "=r"(r3) : "r"(addr));
}

// ---------------- Kernel 1: tensor-core QKV projection v3 ----------------
// grid (6, 64): bx = 64 contiguous W rows (4 warps x m16), by = 64-token supertile
// processed as two 32-token tiles with double-buffered x smem; W staged once.
// x-tile1 LDGs issue before tile0 compute -> latency hidden under HMMA work.
#define WSTR 136
#define XSTR 40

__global__ void __launch_bounds__(128) qkv_proj_kernel(const float* __restrict__ x,
                                                       const float* __restrict__ W) {
    __shared__ __align__(16) __half Wsm[64 * WSTR];       // 17408 B
    __shared__ __align__(16) __half xsm[2][DM * XSTR];    // 20480 B
    const int tid  = threadIdx.x;
    const int w    = tid >> 5;
    const int lane = tid & 31;
    const int gr   = lane >> 2;
    const int tg   = lane & 3;

    const int mrow0 = blockIdx.x * 64;            // W row base (contiguous 32 KB)
    const int nt0   = blockIdx.y * 64;            // token base (2 tiles of 32)
    const int group = blockIdx.x * 4 + w;         // 0..23
    const int head  = group / 3;
    const int type  = group % 3;                  // 0=q 1=k 2=v

    // batched LDGs: all of W + x tile0 in flight together
    float4 wv[16];
    const float4* Wg = reinterpret_cast<const float4*>(W + mrow0 * DM);
#pragma unroll
    for (int j = 0; j < 16; ++j) wv[j] = Wg[tid + j * 128];
    const float4* xr = reinterpret_cast<const float4*>(x + tid * N_TOK + nt0);
    float4 xv[8];
#pragma unroll
    for (int j = 0; j < 8; ++j) xv[j] = xr[j];

    // STS W (q rows pre-scaled)
#pragma unroll
    for (int j = 0; j < 16; ++j) {
        int idx = tid + j * 128;
        int row = idx >> 5;
        int c4  = idx & 31;
        float s = ((((mrow0 + row) >> 4) % 3) == 0) ? QSCL : 1.f;
        *reinterpret_cast<uint2*>(&Wsm[row * WSTR + c4 * 4]) =
            make_uint2(cvt_h2(wv[j].y * s, wv[j].x * s), cvt_h2(wv[j].w * s, wv[j].z * s));
    }
    // STS x tile0
#pragma unroll
    for (int j = 0; j < 8; ++j)
        *reinterpret_cast<uint2*>(&xsm[0][tid * XSTR + 4 * j]) =
            make_uint2(cvt_h2(xv[j].y, xv[j].x), cvt_h2(xv[j].w, xv[j].z));
    __syncthreads();

    // issue x tile1 LDGs now; latency hides under tile0 compute
    float4 xw[8];
#pragma unroll
    for (int j = 0; j < 8; ++j) xw[j] = xr[j + 8];

    // A-frags from Wsm (held for both tiles)
    const uint32_t lmA =
        (uint32_t)__cvta_generic_to_shared(Wsm) +
        ((w * 16 + (lane & 7) + ((lane >> 3) & 1) * 8) * WSTR + (lane >> 4) * 8) * 2;
    uint32_t af[8][4];
#pragma unroll
    for (int ks = 0; ks < 8; ++ks)
        ldsm4(af[ks][0], af[ks][1], af[ks][2], af[ks][3], lmA + ks * 32);

    float acc[2][4][4];
#pragma unroll
    for (int t = 0; t < 2; ++t)
#pragma unroll
        for (int nb = 0; nb < 4; ++nb)
#pragma unroll
            for (int i = 0; i < 4; ++i) acc[t][nb][i] = 0.f;

    // compute tile0
    {
        const uint32_t lmB =
            (uint32_t)__cvta_generic_to_shared(&xsm[0][0]) +
            ((lane & 15) * XSTR + (lane >> 4) * 8) * 2;
#pragma unroll
        for (int ks = 0; ks < 8; ++ks) {
            uint32_t b[4][2];
#pragma unroll
            for (int nc = 0; nc < 2; ++nc) {
                const uint32_t a = lmB + (ks * 16 * XSTR + nc * 16) * 2;
                ldsm4t(b[2 * nc][0], b[2 * nc][1], b[2 * nc + 1][0], b[2 * nc + 1][1], a);
            }
#pragma unroll
            for (int nb = 0; nb < 4; ++nb)
                hmma(acc[0][nb][0], acc[0][nb][1], acc[0][nb][2], acc[0][nb][3],
                     af[ks][0], af[ks][1], af[ks][2], af[ks][3], b[nb][0], b[nb][1]);
        }
    }

    // STS x tile1, then compute tile1
#pragma unroll
    for (int j = 0; j < 8; ++j)
        *reinterpret_cast<uint2*>(&xsm[1][tid * XSTR + 4 * j]) =
            make_uint2(cvt_h2(xw[j].y, xw[j].x), cvt_h2(xw[j].w, xw[j].z));
    __syncthreads();
    {
        const uint32_t lmB =
            (uint32_t)__cvta_generic_to_shared(&xsm[1][0]) +
            ((lane & 15) * XSTR + (lane >> 4) * 8) * 2;
#pragma unroll
        for (int ks = 0; ks < 8; ++ks) {
            uint32_t b[4][2];
#pragma unroll
            for (int nc = 0; nc < 2; ++nc) {
                const uint32_t a = lmB + (ks * 16 * XSTR + nc * 16) * 2;
                ldsm4t(b[2 * nc][0], b[2 * nc][1], b[2 * nc + 1][0], b[2 * nc + 1][1], a);
            }
#pragma unroll
            for (int nb = 0; nb < 4; ++nb)
                hmma(acc[1][nb][0], acc[1][nb][1], acc[1][nb][2], acc[1][nb][3],
                     af[ks][0], af[ks][1], af[ks][2], af[ks][3], b[nb][0], b[nb][1]);
        }
    }

    // epilogue (both tiles)
#pragma unroll
    for (int t = 0; t < 2; ++t) {
        const int tb = nt0 + t * 32;
        if (type < 2) {
            __half* base = (type == 0 ? g_qT : g_kT) + head * N_TOK * DH;
#pragma unroll
            for (int nb = 0; nb < 4; ++nb) {
                const int t0 = tb + nb * 8 + 2 * tg;
                base[t0 * DH + gr]           = __float2half(acc[t][nb][0]);
                base[(t0 + 1) * DH + gr]     = __float2half(acc[t][nb][1]);
                base[t0 * DH + gr + 8]       = __float2half(acc[t][nb][2]);
                base[(t0 + 1) * DH + gr + 8] = __float2half(acc[t][nb][3]);
            }
        } else {
#pragma unroll
            for (int nb = 0; nb < 4; ++nb) {
                const int t0 = tb + nb * 8 + 2 * tg;
                *reinterpret_cast<uint32_t*>(&g_v[(head * DH + gr) * N_TOK + t0]) =
                    cvt_h2(acc[t][nb][1], acc[t][nb][0]);
                *reinterpret_cast<uint32_t*>(&g_v[(head * DH + gr + 8) * N_TOK + t0]) =
                    cvt_h2(acc[t][nb][3], acc[t][nb][2]);
            }
        }
    }
}

// ---------------- Kernel 2: fp16 mma flash attention, split-KV x4 ----------------
// grid 1024: head = bx>>7, rowblock = (bx>>2)&31, split = bx&3.
// CTA 128 thr = 4 warps x 32 rows. Ksm [tok][d] stride 12, Vsm [d][tok] stride 76.
#define KSTR 12
#define VSTR 76
#define COLS_PER_SPLIT (N_TOK / NSPLIT)

__global__ void __launch_bounds__(128, 6) attn_kernel() {
    __shared__ __align__(16) uint32_t Ksm[128 * KSTR];   // 6144 B
    __shared__ __align__(16) uint32_t Vsm[16 * VSTR];    // 4864 B

    const int tid  = threadIdx.x;
    const int w    = tid >> 5;
    const int lane = tid & 31;
    const int gr   = lane >> 2;
    const int tg   = lane & 3;
    const int head  = blockIdx.x >> 7;
    const int r0    = ((blockIdx.x >> 2) & 31) * 128 + w * 32;
    const int split = blockIdx.x & 3;
    const int jt0   = split * COLS_PER_SPLIT;

    uint32_t qa[2][4];
    const __half* qbase = g_qT + head * N_TOK * DH;
#pragma unroll
    for (int m = 0; m < 2; ++m) {
        int rA = r0 + m * 16 + gr;
        qa[m][0] = *reinterpret_cast<const uint32_t*>(qbase + rA * DH + 2 * tg);
        qa[m][1] = *reinterpret_cast<const uint32_t*>(qbase + (rA + 8) * DH + 2 * tg);
        qa[m][2] = *reinterpret_cast<const uint32_t*>(qbase + rA * DH + 2 * tg + 8);
        qa[m][3] = *reinterpret_cast<const uint32_t*>(qbase + (rA + 8) * DH + 2 * tg + 8);
    }

    float o[2][2][4];
    float dn[2][4];
#pragma unroll
    for (int m = 0; m < 2; ++m)
#pragma unroll
        for (int i = 0; i < 4; ++i) { o[m][0][i] = 0.f; o[m][1][i] = 0.f; dn[m][i] = 0.f; }
    const uint32_t ones = (gr == 0) ? 0x3C003C00u : 0u;

    for (int jt = jt0; jt < jt0 + COLS_PER_SPLIT; jt += 128) {
        __syncthreads();
        {   // stage K: thread -> one token (32B)
            const uint4* s = reinterpret_cast<const uint4*>(g_kT + (head * N_TOK + jt + tid) * DH);
            uint4 k0 = s[0], k1 = s[1];
            *reinterpret_cast<uint4*>(&Ksm[tid * KSTR])     = k0;
            *reinterpret_cast<uint4*>(&Ksm[tid * KSTR + 4]) = k1;
        }
        {   // stage V
            int d = tid >> 3, ch = tid & 7;
            const uint4* s = reinterpret_cast<const uint4*>(g_v + (head * DH + d) * N_TOK + jt + ch * 16);
            uint4 v0 = s[0], v1 = s[1];
            *reinterpret_cast<uint4*>(&Vsm[d * VSTR + ch * 8])     = v0;
            *reinterpret_cast<uint4*>(&Vsm[d * VSTR + ch * 8 + 4]) = v1;
        }
        __syncthreads();

#pragma unroll 2
        for (int s = 0; s < 8; ++s) {
            uint32_t pa[2][4];
#pragma unroll
            for (int hlf = 0; hlf < 2; ++hlf) {
                const int nt = 2 * s + hlf;
                const uint32_t b0 = Ksm[(nt * 8 + gr) * KSTR + tg];
                const uint32_t b1 = Ksm[(nt * 8 + gr) * KSTR + tg + 4];
#pragma unroll
                for (int m = 0; m < 2; ++m) {
                    float c0 = 0.f, c1 = 0.f, c2 = 0.f, c3 = 0.f;
                    hmma(c0, c1, c2, c3, qa[m][0], qa[m][1], qa[m][2], qa[m][3], b0, b1);
                    pa[m][hlf * 2]     = ex2_h2(cvt_h2(c1, c0));
                    pa[m][hlf * 2 + 1] = ex2_h2(cvt_h2(c3, c2));
                }
            }
#pragma unroll
            for (int m = 0; m < 2; ++m)
                hmma(dn[m][0], dn[m][1], dn[m][2], dn[m][3],
                     pa[m][0], pa[m][1], pa[m][2], pa[m][3], ones, ones);
#pragma unroll
            for (int nb = 0; nb < 2; ++nb) {
                const uint32_t b0 = Vsm[(nb * 8 + gr) * VSTR + s * 8 + tg];
                const uint32_t b1 = Vsm[(nb * 8 + gr) * VSTR + s * 8 + tg + 4];
#pragma unroll
                for (int m = 0; m < 2; ++m)
                    hmma(o[m][nb][0], o[m][nb][1], o[m][nb][2], o[m][nb][3],
                         pa[m][0], pa[m][1], pa[m][2], pa[m][3], b0, b1);
            }
        }
    }

    // write partials (no divide)
#pragma unroll
    for (int m = 0; m < 2; ++m) {
        const int rA = r0 + m * 16 + gr;
        if (tg == 0) {
            g_pden[split][head][rA]     = dn[m][0];
            g_pden[split][head][rA + 8] = dn[m][2];
        }
#pragma unroll
        for (int nb = 0; nb < 2; ++nb) {
            const int d0 = nb * 8 + 2 * tg;
            g_pnum[split][head][d0][rA]         = o[m][nb][0];
            g_pnum[split][head][d0 + 1][rA]     = o[m][nb][1];
            g_pnum[split][head][d0][rA + 8]     = o[m][nb][2];
            g_pnum[split][head][d0 + 1][rA + 8] = o[m][nb][3];
        }
    }
}

// ---------------- Kernel 3: combine splits ----------------
__global__ void __launch_bounds__(256) combine_kernel(float* __restrict__ out) {
    int g = blockIdx.x * 256 + threadIdx.x;        // 131072 float4 items
    int h = g / (DH * 1024);
    int rem = g % (DH * 1024);
    int d = rem / 1024;
    int t = (rem % 1024) * 4;

    float4 ns = make_float4(0.f, 0.f, 0.f, 0.f);
    float4 es = make_float4(0.f, 0.f, 0.f, 0.f);
#pragma unroll
    for (int sp = 0; sp < NSPLIT; ++sp) {
        float4 nv = *reinterpret_cast<const float4*>(&g_pnum[sp][h][d][t]);
        float4 ev = *reinterpret_cast<const float4*>(&g_pden[sp][h][t]);
        ns.x += nv.x; ns.y += nv.y; ns.z += nv.z; ns.w += nv.w;
        es.x += ev.x; es.y += ev.y; es.z += ev.z; es.w += ev.w;
    }
    float4 r = make_float4(__fdividef(ns.x, es.x), __fdividef(ns.y, es.y),
                           __fdividef(ns.z, es.z), __fdividef(ns.w, es.w));
    *reinterpret_cast<float4*>(&out[(h * DH + d) * N_TOK + t]) = r;
}

extern "C" void kernel_launch(void* const* d_in, const int* in_sizes, int n_in,
                              void* d_out, int out_size) {
    const float* x = (const float*)d_in[0];   // (1,128,64,64) -> [c][n]
    const float* W = (const float*)d_in[1];   // (384,128)
    float* out = (float*)d_out;

    qkv_proj_kernel<<<dim3(6, 64), 128>>>(x, W);
    attn_kernel<<<NH * 32 * NSPLIT, 128>>>();                 // 1024 CTAs
    combine_kernel<<<(NH * DH * 1024) / 256, 256>>>(out);     // 512 CTAs
}

// round 15
// speedup vs baseline: 1.0059x; 1.0059x over previous
#include <cuda_runtime.h>
#include <cuda_fp16.h>
#include <cstdint>

#define N_TOK 4096
#define NH 8
#define DH 16
#define DM 128
#define NSPLIT 4
// (1/sqrt(128)) * log2(e): softmax in exp2 domain
#define QSCL 0.12751743f

// fp16 scratch written by projection
__device__ __half g_qT[NH * N_TOK * DH];   // [head][tok][d]  (q, pre-scaled)
__device__ __half g_kT[NH * N_TOK * DH];   // [head][tok][d]
__device__ __half g_v [NH * DH * N_TOK];   // [head*16+d][tok]
// split-KV partials
__device__ float g_pnum[NSPLIT][NH][DH][N_TOK];   // 8 MB
__device__ float g_pden[NSPLIT][NH][N_TOK];       // 512 KB

// ---------------- helpers ----------------
__device__ __forceinline__ uint32_t cvt_h2(float hi, float lo) {
    uint32_t d;
    asm("cvt.rn.f16x2.f32 %0, %1, %2;" : "=r"(d) : "f"(hi), "f"(lo));
    return d;
}
__device__ __forceinline__ uint32_t ex2_h2(uint32_t a) {
    uint32_t d;
    asm("ex2.approx.f16x2 %0, %1;" : "=r"(d) : "r"(a));
    return d;
}
__device__ __forceinline__ void hmma(float& c0, float& c1, float& c2, float& c3,
                                     uint32_t a0, uint32_t a1, uint32_t a2, uint32_t a3,
                                     uint32_t b0, uint32_t b1) {
    asm volatile("mma.sync.aligned.m16n8k16.row.col.f32.f16.f16.f32 "
                 "{%0,%1,%2,%3}, {%4,%5,%6,%7}, {%8,%9}, {%0,%1,%2,%3};"
                 : "+f"(c0), "+f"(c1), "+f"(c2), "+f"(c3)
                 : "r"(a0), "r"(a1), "r"(a2), "r"(a3), "r"(b0), "r"(b1));
}
__device__ __forceinline__ void ldsm4(uint32_t& r0, uint32_t& r1,
                                      uint32_t& r2, uint32_t& r3, uint32_t addr) {
    asm volatile("ldmatrix.sync.aligned.m8n8.x4.shared.b16 {%0,%1,%2,%3}, [%4];"
                 : "=r"(r0), "=r"(r1), "=r"(r2), "=r"(r3) : "r"(addr));
}
__device__ __forceinline__ void ldsm4t(uint32_t& r0, uint32_t& r1,
                                       uint32_t& r2, uint32_t& r3, uint32_t addr) {
    asm volatile("ldmatrix.sync.aligned.m8n8.x4.trans.shared.b16 {%0,%1,%2,%3}, [%4];"
                 : "=r"(r0), "=r"(r1), "=r"(r2), "=r"(r3) : "r"(addr));
}
// PDL primitives
__device__ __forceinline__ void gdc_wait() {
    asm volatile("griddepcontrol.wait;" ::: "memory");
}
__device__ __forceinline__ void gdc_launch() {
    asm volatile("griddepcontrol.launch_dependents;" ::: "memory");
}

// ---------------- Kernel 1: tensor-core QKV projection v3 ----------------
// grid (6, 64): bx = 64 contiguous W rows (4 warps x m16), by = 64-token supertile
// processed as two 32-token tiles with double-buffered x smem; W staged once.
#define WSTR 136
#define XSTR 40

__global__ void __launch_bounds__(128) qkv_proj_kernel(const float* __restrict__ x,
                                                       const float* __restrict__ W) {
    __shared__ __align__(16) __half Wsm[64 * WSTR];       // 17408 B
    __shared__ __align__(16) __half xsm[2][DM * XSTR];    // 20480 B
    const int tid  = threadIdx.x;
    const int w    = tid >> 5;
    const int lane = tid & 31;
    const int gr   = lane >> 2;
    const int tg   = lane & 3;

    const int mrow0 = blockIdx.x * 64;            // W row base (contiguous 32 KB)
    const int nt0   = blockIdx.y * 64;            // token base (2 tiles of 32)
    const int group = blockIdx.x * 4 + w;         // 0..23
    const int head  = group / 3;
    const int type  = group % 3;                  // 0=q 1=k 2=v

    // batched LDGs: all of W + x tile0 in flight together
    float4 wv[16];
    const float4* Wg = reinterpret_cast<const float4*>(W + mrow0 * DM);
#pragma unroll
    for (int j = 0; j < 16; ++j) wv[j] = Wg[tid + j * 128];
    const float4* xr = reinterpret_cast<const float4*>(x + tid * N_TOK + nt0);
    float4 xv[8];
#pragma unroll
    for (int j = 0; j < 8; ++j) xv[j] = xr[j];

    // STS W (q rows pre-scaled)
#pragma unroll
    for (int j = 0; j < 16; ++j) {
        int idx = tid + j * 128;
        int row = idx >> 5;
        int c4  = idx & 31;
        float s = ((((mrow0 + row) >> 4) % 3) == 0) ? QSCL : 1.f;
        *reinterpret_cast<uint2*>(&Wsm[row * WSTR + c4 * 4]) =
            make_uint2(cvt_h2(wv[j].y * s, wv[j].x * s), cvt_h2(wv[j].w * s, wv[j].z * s));
    }
    // STS x tile0
#pragma unroll
    for (int j = 0; j < 8; ++j)
        *reinterpret_cast<uint2*>(&xsm[0][tid * XSTR + 4 * j]) =
            make_uint2(cvt_h2(xv[j].y, xv[j].x), cvt_h2(xv[j].w, xv[j].z));
    __syncthreads();

    // issue x tile1 LDGs now; latency hides under tile0 compute
    float4 xw[8];
#pragma unroll
    for (int j = 0; j < 8; ++j) xw[j] = xr[j + 8];

    // A-frags from Wsm (held for both tiles)
    const uint32_t lmA =
        (uint32_t)__cvta_generic_to_shared(Wsm) +
        ((w * 16 + (lane & 7) + ((lane >> 3) & 1) * 8) * WSTR + (lane >> 4) * 8) * 2;
    uint32_t af[8][4];
#pragma unroll
    for (int ks = 0; ks < 8; ++ks)
        ldsm4(af[ks][0], af[ks][1], af[ks][2], af[ks][3], lmA + ks * 32);

    float acc[2][4][4];
#pragma unroll
    for (int t = 0; t < 2; ++t)
#pragma unroll
        for (int nb = 0; nb < 4; ++nb)
#pragma unroll
            for (int i = 0; i < 4; ++i) acc[t][nb][i] = 0.f;

    // compute tile0
    {
        const uint32_t lmB =
            (uint32_t)__cvta_generic_to_shared(&xsm[0][0]) +
            ((lane & 15) * XSTR + (lane >> 4) * 8) * 2;
#pragma unroll
        for (int ks = 0; ks < 8; ++ks) {
            uint32_t b[4][2];
#pragma unroll
            for (int nc = 0; nc < 2; ++nc) {
                const uint32_t a = lmB + (ks * 16 * XSTR + nc * 16) * 2;
                ldsm4t(b[2 * nc][0], b[2 * nc][1], b[2 * nc + 1][0], b[2 * nc + 1][1], a);
            }
#pragma unroll
            for (int nb = 0; nb < 4; ++nb)
                hmma(acc[0][nb][0], acc[0][nb][1], acc[0][nb][2], acc[0][nb][3],
                     af[ks][0], af[ks][1], af[ks][2], af[ks][3], b[nb][0], b[nb][1]);
        }
    }

    // STS x tile1, then compute tile1
#pragma unroll
    for (int j = 0; j < 8; ++j)
        *reinterpret_cast<uint2*>(&xsm[1][tid * XSTR + 4 * j]) =
            make_uint2(cvt_h2(xw[j].y, xw[j].x), cvt_h2(xw[j].w, xw[j].z));
    __syncthreads();
    {
        const uint32_t lmB =
            (uint32_t)__cvta_generic_to_shared(&xsm[1][0]) +
            ((lane & 15) * XSTR + (lane >> 4) * 8) * 2;
#pragma unroll
        for (int ks = 0; ks < 8; ++ks) {
            uint32_t b[4][2];
#pragma unroll
            for (int nc = 0; nc < 2; ++nc) {
                const uint32_t a = lmB + (ks * 16 * XSTR + nc * 16) * 2;
                ldsm4t(b[2 * nc][0], b[2 * nc][1], b[2 * nc + 1][0], b[2 * nc + 1][1], a);
            }
#pragma unroll
            for (int nb = 0; nb < 4; ++nb)
                hmma(acc[1][nb][0], acc[1][nb][1], acc[1][nb][2], acc[1][nb][3],
                     af[ks][0], af[ks][1], af[ks][2], af[ks][3], b[nb][0], b[nb][1]);
        }
    }

    // epilogue (both tiles)
#pragma unroll
    for (int t = 0; t < 2; ++t) {
        const int tb = nt0 + t * 32;
        if (type < 2) {
            __half* base = (type == 0 ? g_qT : g_kT) + head * N_TOK * DH;
#pragma unroll
            for (int nb = 0; nb < 4; ++nb) {
                const int t0 = tb + nb * 8 + 2 * tg;
                base[t0 * DH + gr]           = __float2half(acc[t][nb][0]);
                base[(t0 + 1) * DH + gr]     = __float2half(acc[t][nb][1]);
                base[t0 * DH + gr + 8]       = __float2half(acc[t][nb][2]);
                base[(t0 + 1) * DH + gr + 8] = __float2half(acc[t][nb][3]);
            }
        } else {
#pragma unroll
            for (int nb = 0; nb < 4; ++nb) {
                const int t0 = tb + nb * 8 + 2 * tg;
                *reinterpret_cast<uint32_t*>(&g_v[(head * DH + gr) * N_TOK + t0]) =
                    cvt_h2(acc[t][nb][1], acc[t][nb][0]);
                *reinterpret_cast<uint32_t*>(&g_v[(head * DH + gr + 8) * N_TOK + t0]) =
                    cvt_h2(acc[t][nb][3], acc[t][nb][2]);
            }
        }
    }
    gdc_launch();   // signal: this CTA's stores are ready for dependents
}

// ---------------- Kernel 2: fp16 mma flash attention, split-KV x4 ----------------
// grid 1024: head = bx>>7, rowblock = (bx>>2)&31, split = bx&3.
// CTA 128 thr = 4 warps x 32 rows. Ksm [tok][d] stride 12, Vsm [d][tok] stride 76.
#define KSTR 12
#define VSTR 76
#define COLS_PER_SPLIT (N_TOK / NSPLIT)

__global__ void __launch_bounds__(128, 6) attn_kernel() {
    __shared__ __align__(16) uint32_t Ksm[128 * KSTR];   // 6144 B
    __shared__ __align__(16) uint32_t Vsm[16 * VSTR];    // 4864 B

    const int tid  = threadIdx.x;
    const int w    = tid >> 5;
    const int lane = tid & 31;
    const int gr   = lane >> 2;
    const int tg   = lane & 3;
    const int head  = blockIdx.x >> 7;
    const int r0    = ((blockIdx.x >> 2) & 31) * 128 + w * 32;
    const int split = blockIdx.x & 3;
    const int jt0   = split * COLS_PER_SPLIT;

    gdc_wait();   // PDL: wait for projection's stores to be visible

    uint32_t qa[2][4];
    const __half* qbase = g_qT + head * N_TOK * DH;
#pragma unroll
    for (int m = 0; m < 2; ++m) {
        int rA = r0 + m * 16 + gr;
        qa[m][0] = *reinterpret_cast<const uint32_t*>(qbase + rA * DH + 2 * tg);
        qa[m][1] = *reinterpret_cast<const uint32_t*>(qbase + (rA + 8) * DH + 2 * tg);
        qa[m][2] = *reinterpret_cast<const uint32_t*>(qbase + rA * DH + 2 * tg + 8);
        qa[m][3] = *reinterpret_cast<const uint32_t*>(qbase + (rA + 8) * DH + 2 * tg + 8);
    }

    float o[2][2][4];
    float dn[2][4];
#pragma unroll
    for (int m = 0; m < 2; ++m)
#pragma unroll
        for (int i = 0; i < 4; ++i) { o[m][0][i] = 0.f; o[m][1][i] = 0.f; dn[m][i] = 0.f; }
    const uint32_t ones = (gr == 0) ? 0x3C003C00u : 0u;

    for (int jt = jt0; jt < jt0 + COLS_PER_SPLIT; jt += 128) {
        __syncthreads();
        {   // stage K: thread -> one token (32B)
            const uint4* s = reinterpret_cast<const uint4*>(g_kT + (head * N_TOK + jt + tid) * DH);
            uint4 k0 = s[0], k1 = s[1];
            *reinterpret_cast<uint4*>(&Ksm[tid * KSTR])     = k0;
            *reinterpret_cast<uint4*>(&Ksm[tid * KSTR + 4]) = k1;
        }
        {   // stage V
            int d = tid >> 3, ch = tid & 7;
            const uint4* s = reinterpret_cast<const uint4*>(g_v + (head * DH + d) * N_TOK + jt + ch * 16);
            uint4 v0 = s[0], v1 = s[1];
            *reinterpret_cast<uint4*>(&Vsm[d * VSTR + ch * 8])     = v0;
            *reinterpret_cast<uint4*>(&Vsm[d * VSTR + ch * 8 + 4]) = v1;
        }
        __syncthreads();

#pragma unroll 2
        for (int s = 0; s < 8; ++s) {
            uint32_t pa[2][4];
#pragma unroll
            for (int hlf = 0; hlf < 2; ++hlf) {
                const int nt = 2 * s + hlf;
                const uint32_t b0 = Ksm[(nt * 8 + gr) * KSTR + tg];
                const uint32_t b1 = Ksm[(nt * 8 + gr) * KSTR + tg + 4];
#pragma unroll
                for (int m = 0; m < 2; ++m) {
                    float c0 = 0.f, c1 = 0.f, c2 = 0.f, c3 = 0.f;
                    hmma(c0, c1, c2, c3, qa[m][0], qa[m][1], qa[m][2], qa[m][3], b0, b1);
                    pa[m][hlf * 2]     = ex2_h2(cvt_h2(c1, c0));
                    pa[m][hlf * 2 + 1] = ex2_h2(cvt_h2(c3, c2));
                }
            }
#pragma unroll
            for (int m = 0; m < 2; ++m)
                hmma(dn[m][0], dn[m][1], dn[m][2], dn[m][3],
                     pa[m][0], pa[m][1], pa[m][2], pa[m][3], ones, ones);
#pragma unroll
            for (int nb = 0; nb < 2; ++nb) {
                const uint32_t b0 = Vsm[(nb * 8 + gr) * VSTR + s * 8 + tg];
                const uint32_t b1 = Vsm[(nb * 8 + gr) * VSTR + s * 8 + tg + 4];
#pragma unroll
                for (int m = 0; m < 2; ++m)
                    hmma(o[m][nb][0], o[m][nb][1], o[m][nb][2], o[m][nb][3],
                         pa[m][0], pa[m][1], pa[m][2], pa[m][3], b0, b1);
            }
        }
    }

    // write partials (no divide)
#pragma unroll
    for (int m = 0; m < 2; ++m) {
        const int rA = r0 + m * 16 + gr;
        if (tg == 0) {
            g_pden[split][head][rA]     = dn[m][0];
            g_pden[split][head][rA + 8] = dn[m][2];
        }
#pragma unroll
        for (int nb = 0; nb < 2; ++nb) {
            const int d0 = nb * 8 + 2 * tg;
            g_pnum[split][head][d0][rA]         = o[m][nb][0];
            g_pnum[split][head][d0 + 1][rA]     = o[m][nb][1];
            g_pnum[split][head][d0][rA + 8]     = o[m][nb][2];
            g_pnum[split][head][d0 + 1][rA + 8] = o[m][nb][3];
        }
    }
    gdc_launch();
}

// ---------------- Kernel 3: combine splits ----------------
__global__ void __launch_bounds__(256) combine_kernel(float* __restrict__ out) {
    int g = blockIdx.x * 256 + threadIdx.x;        // 131072 float4 items
    int h = g / (DH * 1024);
    int rem = g % (DH * 1024);
    int d = rem / 1024;
    int t = (rem % 1024) * 4;

    gdc_wait();   // PDL: wait for attention partials

    float4 ns = make_float4(0.f, 0.f, 0.f, 0.f);
    float4 es = make_float4(0.f, 0.f, 0.f, 0.f);
#pragma unroll
    for (int sp = 0; sp < NSPLIT; ++sp) {
        float4 nv = *reinterpret_cast<const float4*>(&g_pnum[sp][h][d][t]);
        float4 ev = *reinterpret_cast<const float4*>(&g_pden[sp][h][t]);
        ns.x += nv.x; ns.y += nv.y; ns.z += nv.z; ns.w += nv.w;
        es.x += ev.x; es.y += ev.y; es.z += ev.z; es.w += ev.w;
    }
    float4 r = make_float4(__fdividef(ns.x, es.x), __fdividef(ns.y, es.y),
                           __fdividef(ns.z, es.z), __fdividef(ns.w, es.w));
    *reinterpret_cast<float4*>(&out[(h * DH + d) * N_TOK + t]) = r;
}

extern "C" void kernel_launch(void* const* d_in, const int* in_sizes, int n_in,
                              void* d_out, int out_size) {
    const float* x = (const float*)d_in[0];   // (1,128,64,64) -> [c][n]
    const float* W = (const float*)d_in[1];   // (384,128)
    float* out = (float*)d_out;

    qkv_proj_kernel<<<dim3(6, 64), 128>>>(x, W);

    cudaLaunchAttribute pdl[1];
    pdl[0].id = cudaLaunchAttributeProgrammaticStreamSerialization;
    pdl[0].val.programmaticStreamSerializationAllowed = 1;

    {   // attn with PDL
        cudaLaunchConfig_t cfg = {};
        cfg.gridDim  = dim3(NH * 32 * NSPLIT);
        cfg.blockDim = dim3(128);
        cfg.attrs = pdl;
        cfg.numAttrs = 1;
        cudaLaunchKernelEx(&cfg, attn_kernel);
    }
    {   // combine with PDL
        cudaLaunchConfig_t cfg = {};
        cfg.gridDim  = dim3((NH * DH * 1024) / 256);
        cfg.blockDim = dim3(256);
        cfg.attrs = pdl;
        cfg.numAttrs = 1;
        cudaLaunchKernelEx(&cfg, combine_kernel, out);
    }
}